// round 3
// baseline (speedup 1.0000x reference)
#include <cuda_runtime.h>

#define D 64
#define L 64
#define BB 8
#define MAT (D*D)          // 4096 floats per matrix
#define NMAT (BB*L)        // 512 matrices
#define PA 68              // padded smem pitch for A (kills bank conflicts)

// All matrices in reciprocal-exp domain: W = exp(-m).
// log-semiring matmul:  out[i,j] = rcp( sum_k rcp( A[i,k] + B[k,j] ) )
__device__ float g_buf0[NMAT * MAT];   // 8MB
__device__ float g_buf1[NMAT * MAT];   // 8MB
__device__ float g_wtab[4 * MAT];      // exp(-p[a+1])
__device__ float g_ttab[16 * MAT];     // pair products  W(a) (x) W(b)
__device__ float g_qtab[256 * MAT];    // quad products  pair (x) pair
__device__ float g_p0tab[MAT];         // exp(-p[0])

__device__ __forceinline__ float frcp(float x) {
    float r;
    asm("rcp.approx.f32 %0, %1;" : "=f"(r) : "f"(x));
    return r;
}

// One k-step for 4 output columns using packed f32x2 adds:
//   acc01 += rcp(a + b0), rcp(a + b1);  acc23 += rcp(a + b2), rcp(a + b3)
// b01/b23 hold (b0,b1)/(b2,b3) as f32x2 in u64 carriers.
__device__ __forceinline__ void step2(float a,
                                      unsigned long long b01,
                                      unsigned long long b23,
                                      unsigned long long& acc01,
                                      unsigned long long& acc23) {
    asm("{\n\t"
        ".reg .b64 aa, s01, s23, r01, r23;\n\t"
        ".reg .f32 s0,s1,s2,s3,r0,r1,r2,r3;\n\t"
        "mov.b64 aa, {%4,%4};\n\t"
        "add.rn.f32x2 s01, aa, %2;\n\t"
        "add.rn.f32x2 s23, aa, %3;\n\t"
        "mov.b64 {s0,s1}, s01;\n\t"
        "mov.b64 {s2,s3}, s23;\n\t"
        "rcp.approx.f32 r0, s0;\n\t"
        "rcp.approx.f32 r1, s1;\n\t"
        "rcp.approx.f32 r2, s2;\n\t"
        "rcp.approx.f32 r3, s3;\n\t"
        "mov.b64 r01, {r0,r1};\n\t"
        "mov.b64 r23, {r2,r3};\n\t"
        "add.rn.f32x2 %0, %0, r01;\n\t"
        "add.rn.f32x2 %1, %1, r23;\n\t"
        "}\n"
        : "+l"(acc01), "+l"(acc23)
        : "l"(b01), "l"(b23), "f"(a));
}

// ---------------------------------------------------------------------------
// Quarter matmul: one CTA computes a 64x16 column slice (quarter q) of
// Dst = A (x) B.   256 threads, thread = (row, colgroup of 4).
// ---------------------------------------------------------------------------
__device__ __forceinline__ void mm_quarter(const float* __restrict__ A,
                                           const float* __restrict__ B,
                                           float* __restrict__ Dst, int q) {
    __shared__ float sA[D * PA];       // full A, padded pitch
    __shared__ float sB[D * 16];       // quarter of B
    const int t = threadIdx.x;

    // stage A (4 float4 per thread)
#pragma unroll
    for (int i = 0; i < 4; i++) {
        int idx = t + i * 256;          // float4 index 0..1023
        int r = idx >> 4, c = idx & 15;
        *(float4*)&sA[r * PA + c * 4] = ((const float4*)A)[idx];
    }
    // stage B quarter (1 float4 per thread)
    {
        int k = t >> 2, g = t & 3;
        *(float4*)&sB[k * 16 + g * 4] = *(const float4*)&B[k * D + q * 16 + g * 4];
    }
    __syncthreads();

    const int row = t >> 2, cg = t & 3;
    const float* ap = &sA[row * PA];
    const float* bp = &sB[cg * 4];
    unsigned long long acc01 = 0ull, acc23 = 0ull;   // f32x2 (0,0) pairs
#pragma unroll
    for (int k4 = 0; k4 < 16; k4++) {
        float4 av = *(const float4*)&ap[k4 * 4];
        ulonglong2 b0 = *(const ulonglong2*)&bp[(k4 * 4 + 0) * 16];
        ulonglong2 b1 = *(const ulonglong2*)&bp[(k4 * 4 + 1) * 16];
        ulonglong2 b2 = *(const ulonglong2*)&bp[(k4 * 4 + 2) * 16];
        ulonglong2 b3 = *(const ulonglong2*)&bp[(k4 * 4 + 3) * 16];
        step2(av.x, b0.x, b0.y, acc01, acc23);
        step2(av.y, b1.x, b1.y, acc01, acc23);
        step2(av.z, b2.x, b2.y, acc01, acc23);
        step2(av.w, b3.x, b3.y, acc01, acc23);
    }
    float s0 = __uint_as_float((unsigned)(acc01 & 0xffffffffull));
    float s1 = __uint_as_float((unsigned)(acc01 >> 32));
    float s2 = __uint_as_float((unsigned)(acc23 & 0xffffffffull));
    float s3 = __uint_as_float((unsigned)(acc23 >> 32));
    *(float4*)&Dst[row * D + q * 16 + cg * 4] =
        make_float4(frcp(s0), frcp(s1), frcp(s2), frcp(s3));
}

// ---------------------------------------------------------------------------
// "Latest value" resolver: where does value of index m live before pass 2^slog?
// ---------------------------------------------------------------------------
__device__ __forceinline__ const float* latest(const int* __restrict__ act,
                                               int b, int m, int slog) {
    size_t off = (size_t)(b * L + m) * MAT;
    if (m < 2) return g_buf0 + off;
    int p = 31 - __clz(m);
    if (p > slog - 1) p = slog - 1;
    if (p == 1) {
        if (m == 2) return g_buf1 + off;
        const int* a = act + b * L + (m - 3);
        int idx = ((a[0] * 4 + a[1]) * 4 + a[2]) * 4 + a[3];
        return g_qtab + (size_t)idx * MAT;
    }
    return (p & 1) ? g_buf1 + off : g_buf0 + off;
}

// ---------------------------------------------------------------------------
// Kernels
// ---------------------------------------------------------------------------
__global__ void exp_tab_kernel(const float* __restrict__ p) {
    int a = blockIdx.x;
    const float4* src = (const float4*)(p + (size_t)a * MAT);
    float4* dst = (a == 0) ? (float4*)g_p0tab
                           : (float4*)(g_wtab + (size_t)(a - 1) * MAT);
    for (int i = threadIdx.x; i < MAT / 4; i += 256) {
        float4 v = src[i];
        dst[i] = make_float4(expf(-v.x), expf(-v.y), expf(-v.z), expf(-v.w));
    }
}

// 16 pair products, 4 quarters each = 64 CTAs
__global__ void __launch_bounds__(256, 6) pair_kernel() {
    int pidx = blockIdx.x >> 2, q = blockIdx.x & 3;
    int a = pidx >> 2, b = pidx & 3;
    mm_quarter(g_wtab + (size_t)a * MAT, g_wtab + (size_t)b * MAT,
               g_ttab + (size_t)pidx * MAT, q);
}

// quads (1024) + tris (32) + step-1 copies for l=0,1 (16) = 1072 CTAs
__global__ void __launch_bounds__(256, 6) stage2_kernel(const int* __restrict__ act) {
    int bid = blockIdx.x;
    if (bid < 1024) {
        int qidx = bid >> 2, q = bid & 3;
        mm_quarter(g_ttab + (size_t)(qidx >> 4) * MAT,
                   g_ttab + (size_t)(qidx & 15) * MAT,
                   g_qtab + (size_t)qidx * MAT, q);
    } else if (bid < 1056) {
        int i = bid - 1024;
        int b = i >> 2, q = i & 3;
        int a0 = act[b * L], a12 = act[b * L + 1] * 4 + act[b * L + 2];
        mm_quarter(g_wtab + (size_t)a0 * MAT, g_ttab + (size_t)a12 * MAT,
                   g_buf1 + (size_t)(b * L + 2) * MAT, q);
    } else {
        int i = bid - 1056;                 // 0..15
        int b = i >> 1, which = i & 1;      // l = 0 or 1
        const float* src = which
            ? g_ttab + (size_t)(act[b * L] * 4 + act[b * L + 1]) * MAT
            : g_wtab + (size_t)act[b * L] * MAT;
        float* dst = g_buf0 + (size_t)(b * L + which) * MAT;
        for (int j = threadIdx.x; j < MAT / 4; j += 256)
            ((float4*)dst)[j] = ((const float4*)src)[j];
    }
}

// Doubling pass for step = 2^slog (slog >= 2). No copies; writes only l >= step.
__global__ void __launch_bounds__(256, 6) step_kernel(const int* __restrict__ act,
                                                      int slog) {
    int step = 1 << slog;
    int n = L - step;
    int idx = blockIdx.x >> 2, q = blockIdx.x & 3;
    int b = idx / n;
    int l = step + (idx - b * n);
    const float* A = latest(act, b, l - step, slog);
    const float* Bm = latest(act, b, l, slog);
    float* dstbuf = (slog & 1) ? g_buf1 : g_buf0;
    mm_quarter(A, Bm, dstbuf + (size_t)(b * L + l) * MAT, q);
}

// Final: x = init (x) PM ; y = x (x) p0 ; output in log domain.
__global__ void final_kernel(const int* __restrict__ act,
                             const float* __restrict__ init_vec,
                             float* __restrict__ out) {
    int bl = blockIdx.x;
    int b = bl >> 6, l = bl & 63;
    const float* W = latest(act, b, l, 6);
    __shared__ float ci[D];
    __shared__ float xw[D];
    int t = threadIdx.x;                   // 64 threads
    ci[t] = expf(-init_vec[t]);
    __syncthreads();

    float s = 0.f;
#pragma unroll 8
    for (int k = 0; k < D; k++)
        s += frcp(ci[k] + W[k * D + t]);
    xw[t] = frcp(s);
    __syncthreads();

    float s2 = 0.f;
#pragma unroll 8
    for (int k = 0; k < D; k++)
        s2 += frcp(xw[k] + g_p0tab[k * D + t]);
    out[(size_t)bl * D + t] = logf(s2);
}

extern "C" void kernel_launch(void* const* d_in, const int* in_sizes, int n_in,
                              void* d_out, int out_size) {
    const float* p        = (const float*)d_in[0];  // (5, 64, 64)
    const float* init_vec = (const float*)d_in[1];  // (64,)
    const int*   act      = (const int*)d_in[2];    // (8, 64)
    float* out = (float*)d_out;                     // (8, 64, 64)

    exp_tab_kernel<<<5, 256>>>(p);
    pair_kernel<<<64, 256>>>();
    stage2_kernel<<<1072, 256>>>(act);
    step_kernel<<<8 * (L - 4)  * 4, 256>>>(act, 2);   // 1920 CTAs -> buf0
    step_kernel<<<8 * (L - 8)  * 4, 256>>>(act, 3);   // 1792 CTAs -> buf1
    step_kernel<<<8 * (L - 16) * 4, 256>>>(act, 4);   // 1536 CTAs -> buf0
    step_kernel<<<8 * (L - 32) * 4, 256>>>(act, 5);   // 1024 CTAs -> buf1
    final_kernel<<<512, 64>>>(act, init_vec, out);
}